// round 2
// baseline (speedup 1.0000x reference)
#include <cuda_runtime.h>

// Problem constants
#define BB   8
#define CIN  512
#define MIDC 128
#define NNE  2304   // H*W = 48*48

// Tiling
#define TB 128
#define KB 8

// Scratch: fa, fv, fh, gav, gah, oav, oah (7 x 8*128*2304) + Sav, Sah (2 x 8*2304*2304)
#define FSZ  ((size_t)BB * MIDC * NNE)          // 2,359,296
#define SSZ  ((size_t)BB * NNE * NNE)           // 42,467,328
__device__ float d_scratch[7 * 2359296 + 2 * 42467328];

// ---------------------------------------------------------------------------
// Generic GEMM: Y[b][m][n] = sum_k W[m][k] * X[b][k][n]  (+bias)(+BN-ReLU)(+resid)
// W row-major [M, Kd]; optional per-batch W stride (for o = g @ A).
// M = gridDim.y * TB. All dims multiples of tile sizes (no bounds checks).
// ---------------------------------------------------------------------------
__global__ __launch_bounds__(256) void gemm_wx(
    const float* __restrict__ Wp, size_t wStride, int Kd,
    const float* __restrict__ X,
    const float* __restrict__ bias,
    const float* __restrict__ gamma,
    const float* __restrict__ beta,
    const float* __restrict__ resid,
    float* __restrict__ Y)
{
    const int b  = blockIdx.z;
    const int n0 = blockIdx.x * TB;
    const int m0 = blockIdx.y * TB;
    const int M  = gridDim.y * TB;
    const float* W  = Wp + (size_t)b * wStride;
    const float* Xb = X + (size_t)b * (size_t)Kd * NNE;
    const size_t ybase = (size_t)b * (size_t)M * NNE;

    __shared__ float As[KB][TB];
    __shared__ float Bs[KB][TB];

    const int tid = threadIdx.x;
    const int tx = tid & 15;
    const int ty = tid >> 4;

    float acc[8][8];
#pragma unroll
    for (int i = 0; i < 8; i++)
#pragma unroll
        for (int j = 0; j < 8; j++) acc[i][j] = 0.f;

    // A-load mapping: 256 threads -> 128 m x 2 float4-in-k
    const int a_m  = tid >> 1;
    const int a_k4 = (tid & 1) * 4;
    // B-load mapping: 256 threads -> 8 k x 32 float4-in-n
    const int b_n4 = (tid & 31) * 4;
    const int b_k  = tid >> 5;

    const float* wrow = &W[(size_t)(m0 + a_m) * Kd + a_k4];
    const float* xrow = &Xb[(size_t)b_k * NNE + n0 + b_n4];

    for (int k0 = 0; k0 < Kd; k0 += KB) {
        float4 av = *reinterpret_cast<const float4*>(wrow + k0);
        As[a_k4 + 0][a_m] = av.x;
        As[a_k4 + 1][a_m] = av.y;
        As[a_k4 + 2][a_m] = av.z;
        As[a_k4 + 3][a_m] = av.w;
        *reinterpret_cast<float4*>(&Bs[b_k][b_n4]) =
            *reinterpret_cast<const float4*>(xrow + (size_t)k0 * NNE);
        __syncthreads();
#pragma unroll
        for (int k = 0; k < KB; k++) {
            float a[8], bv[8];
            *reinterpret_cast<float4*>(&a[0])  = *reinterpret_cast<float4*>(&As[k][ty * 4]);
            *reinterpret_cast<float4*>(&a[4])  = *reinterpret_cast<float4*>(&As[k][64 + ty * 4]);
            *reinterpret_cast<float4*>(&bv[0]) = *reinterpret_cast<float4*>(&Bs[k][tx * 4]);
            *reinterpret_cast<float4*>(&bv[4]) = *reinterpret_cast<float4*>(&Bs[k][64 + tx * 4]);
#pragma unroll
            for (int i = 0; i < 8; i++)
#pragma unroll
                for (int j = 0; j < 8; j++)
                    acc[i][j] = fmaf(a[i], bv[j], acc[i][j]);
        }
        __syncthreads();
    }

#pragma unroll
    for (int i = 0; i < 8; i++) {
        const int mi = (i < 4) ? (ty * 4 + i) : (64 + ty * 4 + i - 4);
        const int m  = m0 + mi;
        const float bi = bias ? bias[m] : 0.f;
        float sc = 1.f, sh = 0.f;
        const bool dobn = (gamma != nullptr);
        if (dobn) { sc = gamma[m] * rsqrtf(1.f + 1e-5f); sh = beta[m]; }
        const size_t rb = ybase + (size_t)m * NNE + n0;
#pragma unroll
        for (int j = 0; j < 8; j++) {
            const int nj = (j < 4) ? (tx * 4 + j) : (64 + tx * 4 + j - 4);
            float y = acc[i][j] + bi;
            if (dobn) y = fmaxf(y * sc + sh, 0.f);
            if (resid) y += resid[rb + nj];
            Y[rb + nj] = y;
        }
    }
}

// ---------------------------------------------------------------------------
// S[b][i][j] = scale * sum_k Q[b][k][i] * Kf[b][k][j]   (both k-major, K=128)
// ---------------------------------------------------------------------------
__global__ __launch_bounds__(256) void gemm_s(
    const float* __restrict__ Q, const float* __restrict__ Kf,
    float* __restrict__ S)
{
    const int b  = blockIdx.z;
    const int j0 = blockIdx.x * TB;
    const int i0 = blockIdx.y * TB;
    const float* Qb = Q  + (size_t)b * MIDC * NNE;
    const float* Kb = Kf + (size_t)b * MIDC * NNE;

    __shared__ float As[KB][TB];
    __shared__ float Bs[KB][TB];

    const int tid = threadIdx.x;
    const int tx = tid & 15;
    const int ty = tid >> 4;
    const int l_n4 = (tid & 31) * 4;
    const int l_k  = tid >> 5;

    float acc[8][8];
#pragma unroll
    for (int i = 0; i < 8; i++)
#pragma unroll
        for (int j = 0; j < 8; j++) acc[i][j] = 0.f;

    const float* qrow = &Qb[(size_t)l_k * NNE + i0 + l_n4];
    const float* krow = &Kb[(size_t)l_k * NNE + j0 + l_n4];

    for (int k0 = 0; k0 < MIDC; k0 += KB) {
        *reinterpret_cast<float4*>(&As[l_k][l_n4]) =
            *reinterpret_cast<const float4*>(qrow + (size_t)k0 * NNE);
        *reinterpret_cast<float4*>(&Bs[l_k][l_n4]) =
            *reinterpret_cast<const float4*>(krow + (size_t)k0 * NNE);
        __syncthreads();
#pragma unroll
        for (int k = 0; k < KB; k++) {
            float a[8], bv[8];
            *reinterpret_cast<float4*>(&a[0])  = *reinterpret_cast<float4*>(&As[k][ty * 4]);
            *reinterpret_cast<float4*>(&a[4])  = *reinterpret_cast<float4*>(&As[k][64 + ty * 4]);
            *reinterpret_cast<float4*>(&bv[0]) = *reinterpret_cast<float4*>(&Bs[k][tx * 4]);
            *reinterpret_cast<float4*>(&bv[4]) = *reinterpret_cast<float4*>(&Bs[k][64 + tx * 4]);
#pragma unroll
            for (int i = 0; i < 8; i++)
#pragma unroll
                for (int j = 0; j < 8; j++)
                    acc[i][j] = fmaf(a[i], bv[j], acc[i][j]);
        }
        __syncthreads();
    }

    const float scale = 0.08838834764831845f;  // 128^-0.5
#pragma unroll
    for (int i = 0; i < 8; i++) {
        const int mi = (i < 4) ? (ty * 4 + i) : (64 + ty * 4 + i - 4);
        const size_t rb = (size_t)b * NNE * NNE + (size_t)(i0 + mi) * NNE + j0;
#pragma unroll
        for (int j = 0; j < 8; j++) {
            const int nj = (j < 4) ? (tx * 4 + j) : (64 + tx * 4 + j - 4);
            S[rb + nj] = acc[i][j] * scale;
        }
    }
}

// ---------------------------------------------------------------------------
// In-place row softmax over last dim (rows of length 2304 = 9*256)
// ---------------------------------------------------------------------------
__global__ __launch_bounds__(256) void softmax_rows(float* __restrict__ S)
{
    float* p = S + (size_t)blockIdx.x * NNE;
    const int tid = threadIdx.x;

    float v[9];
    float mx = -3.4e38f;
#pragma unroll
    for (int i = 0; i < 9; i++) { v[i] = p[tid + i * 256]; mx = fmaxf(mx, v[i]); }

    __shared__ float sm[8];
#pragma unroll
    for (int o = 16; o > 0; o >>= 1) mx = fmaxf(mx, __shfl_xor_sync(0xffffffffu, mx, o));
    if ((tid & 31) == 0) sm[tid >> 5] = mx;
    __syncthreads();
    const float m2 = fmaxf(fmaxf(fmaxf(sm[0], sm[1]), fmaxf(sm[2], sm[3])),
                           fmaxf(fmaxf(sm[4], sm[5]), fmaxf(sm[6], sm[7])));

    float s = 0.f;
#pragma unroll
    for (int i = 0; i < 9; i++) { v[i] = __expf(v[i] - m2); s += v[i]; }
#pragma unroll
    for (int o = 16; o > 0; o >>= 1) s += __shfl_xor_sync(0xffffffffu, s, o);
    __syncthreads();
    if ((tid & 31) == 0) sm[tid >> 5] = s;
    __syncthreads();
    const float tot = sm[0] + sm[1] + sm[2] + sm[3] + sm[4] + sm[5] + sm[6] + sm[7];
    const float inv = __frcp_rn(tot);
#pragma unroll
    for (int i = 0; i < 9; i++) p[tid + i * 256] = v[i] * inv;
}

// ---------------------------------------------------------------------------
extern "C" void kernel_launch(void* const* d_in, const int* in_sizes, int n_in,
                              void* d_out, int out_size)
{
    (void)in_sizes; (void)n_in; (void)out_size;

    const float* x    = (const float*)d_in[0];
    const float* x_h  = (const float*)d_in[1];
    const float* x_v  = (const float*)d_in[2];
    const float* Wa   = (const float*)d_in[3];
    const float* ba   = (const float*)d_in[4];
    const float* ga   = (const float*)d_in[5];
    const float* ta   = (const float*)d_in[6];
    const float* Wv   = (const float*)d_in[7];
    const float* bv   = (const float*)d_in[8];
    const float* gv   = (const float*)d_in[9];
    const float* tv   = (const float*)d_in[10];
    const float* Wgav = (const float*)d_in[11];
    const float* bgav = (const float*)d_in[12];
    const float* Wgah = (const float*)d_in[13];
    const float* bgah = (const float*)d_in[14];
    const float* Wfav = (const float*)d_in[15];
    const float* bfav = (const float*)d_in[16];
    const float* Wfah = (const float*)d_in[17];
    const float* bfah = (const float*)d_in[18];

    void* sp = nullptr;
    cudaGetSymbolAddress(&sp, d_scratch);
    float* base = (float*)sp;
    float* fa  = base;
    float* fv  = base + FSZ;
    float* fh  = base + 2 * FSZ;
    float* gav = base + 3 * FSZ;
    float* gah = base + 4 * FSZ;
    float* oav = base + 5 * FSZ;
    float* oah = base + 6 * FSZ;
    float* Sav = base + 7 * FSZ;
    float* Sah = Sav + SSZ;

    float* out_h = (float*)d_out;
    float* out_v = out_h + (size_t)BB * CIN * NNE;

    dim3 blk(256);
    dim3 gIn(NNE / TB, MIDC / TB, BB);   // (18, 1, 8)
    dim3 gOut(NNE / TB, CIN / TB, BB);   // (18, 4, 8)
    dim3 gS(NNE / TB, NNE / TB, BB);     // (18, 18, 8)

    // Input 1x1 convs
    gemm_wx<<<gIn, blk>>>(Wa,   0, CIN, x,   ba,   ga,      ta,      nullptr, fa);
    gemm_wx<<<gIn, blk>>>(Wv,   0, CIN, x_v, bv,   gv,      tv,      nullptr, fv);
    gemm_wx<<<gIn, blk>>>(Wv,   0, CIN, x_h, bv,   gv,      tv,      nullptr, fh);
    gemm_wx<<<gIn, blk>>>(Wgav, 0, CIN, x,   bgav, nullptr, nullptr, nullptr, gav);
    gemm_wx<<<gIn, blk>>>(Wgah, 0, CIN, x,   bgah, nullptr, nullptr, nullptr, gah);

    // Attention scores
    gemm_s<<<gS, blk>>>(fv, fa, Sav);
    gemm_s<<<gS, blk>>>(fh, fa, Sah);

    // Softmax over last dim
    softmax_rows<<<BB * NNE, blk>>>(Sav);
    softmax_rows<<<BB * NNE, blk>>>(Sah);

    // o = g @ A  (per-batch W = g, stride MIDC*NNE)
    gemm_wx<<<gIn, blk>>>(gav, (size_t)MIDC * NNE, NNE, Sav, nullptr, nullptr, nullptr, nullptr, oav);
    gemm_wx<<<gIn, blk>>>(gah, (size_t)MIDC * NNE, NNE, Sah, nullptr, nullptr, nullptr, nullptr, oah);

    // Output convs + residual
    gemm_wx<<<gOut, blk>>>(Wfav, 0, MIDC, oav, bfav, nullptr, nullptr, x, out_v);
    gemm_wx<<<gOut, blk>>>(Wfah, 0, MIDC, oah, bfah, nullptr, nullptr, x, out_h);
}

// round 3
// speedup vs baseline: 1.7056x; 1.7056x over previous
#include <cuda_runtime.h>

typedef unsigned long long u64;

// Problem constants
#define BB   8
#define CIN  512
#define MIDC 128
#define NNE  2304   // H*W
#define TB   128
#define KB   8

#define FSZ  ((size_t)BB * MIDC * NNE)          // 2,359,296
#define SSZ  ((size_t)BB * NNE * NNE)           // 42,467,328
__device__ float d_scratch[7 * 2359296 + 2 * 42467328];

// ---------------------------------------------------------------------------
// f32x2 packed-FMA helpers
// ---------------------------------------------------------------------------
__device__ __forceinline__ u64 bcast2(float x) {
    u64 r; asm("mov.b64 %0, {%1, %1};" : "=l"(r) : "f"(x)); return r;
}
__device__ __forceinline__ void ffma2(u64& d, u64 a, u64 b) {
    asm("fma.rn.f32x2 %0, %1, %2, %3;" : "=l"(d) : "l"(a), "l"(b), "l"(d));
}
__device__ __forceinline__ void unpack2(u64 v, float& x, float& y) {
    asm("mov.b64 {%0, %1}, %2;" : "=f"(x), "=f"(y) : "l"(v));
}
__device__ __forceinline__ void lds2u64(u64& x, u64& y, const float* p) {
    unsigned a = (unsigned)__cvta_generic_to_shared(p);
    asm volatile("ld.shared.v2.b64 {%0, %1}, [%2];" : "=l"(x), "=l"(y) : "r"(a));
}

// ---------------------------------------------------------------------------
// Shared 128x128-tile microkernel step: one KB-deep smem tile -> acc update
// acc[i][j2]: i = m index (8), j2 = packed n pair (4) -> 8x8 outputs/thread
// ---------------------------------------------------------------------------
__device__ __forceinline__ void mma_tile(const float (*Ab)[TB], const float (*Bb)[TB],
                                         int tx, int ty, u64 acc[8][4])
{
#pragma unroll
    for (int k = 0; k < KB; k++) {
        float4 a0 = *reinterpret_cast<const float4*>(&Ab[k][ty * 4]);
        float4 a1 = *reinterpret_cast<const float4*>(&Ab[k][64 + ty * 4]);
        u64 b0, b1, b2, b3;
        lds2u64(b0, b1, &Bb[k][tx * 4]);
        lds2u64(b2, b3, &Bb[k][64 + tx * 4]);
        u64 av[8];
        av[0] = bcast2(a0.x); av[1] = bcast2(a0.y); av[2] = bcast2(a0.z); av[3] = bcast2(a0.w);
        av[4] = bcast2(a1.x); av[5] = bcast2(a1.y); av[6] = bcast2(a1.z); av[7] = bcast2(a1.w);
#pragma unroll
        for (int i = 0; i < 8; i++) {
            ffma2(acc[i][0], av[i], b0);
            ffma2(acc[i][1], av[i], b1);
            ffma2(acc[i][2], av[i], b2);
            ffma2(acc[i][3], av[i], b3);
        }
    }
}

// ---------------------------------------------------------------------------
// Multi-op GEMM: Y[b][m][n] = sum_k W[m][k] * X[b][k][n] (+bias)(+BN-ReLU)(+resid)
// Up to 5 ops per launch (same Kd / nMT across ops). blockIdx.y = op*nMT + mtile.
// ---------------------------------------------------------------------------
struct GOp {
    const float* W; const float* X;
    const float* bias; const float* gamma; const float* beta; const float* resid;
    float* Y; size_t wStride;
};
struct GOps { GOp v[5]; };

__global__ __launch_bounds__(256, 2) void gemm_multi(GOps ops, int nMT, int Kd)
{
    const int b  = blockIdx.z;
    const int n0 = blockIdx.x * TB;
    const int oi = blockIdx.y / nMT;
    const int m0 = (blockIdx.y % nMT) * TB;
    const GOp op = ops.v[oi];
    const int Mtot = nMT * TB;

    const float* W  = op.W + (size_t)b * op.wStride;
    const float* Xb = op.X + (size_t)b * (size_t)Kd * NNE;

    __shared__ float As[2][KB][TB];
    __shared__ float Bs[2][KB][TB];

    const int tid = threadIdx.x;
    const int tx = tid & 15, ty = tid >> 4;
    const int a_m = tid >> 1, a_k4 = (tid & 1) * 4;
    const int b_k = tid >> 5, b_n4 = (tid & 31) * 4;

    const float* wp = W  + (size_t)(m0 + a_m) * Kd + a_k4;
    const float* xp = Xb + (size_t)b_k * NNE + n0 + b_n4;

    u64 acc[8][4];
#pragma unroll
    for (int i = 0; i < 8; i++)
#pragma unroll
        for (int j = 0; j < 4; j++) acc[i][j] = 0ull;

    // Prologue: load tile 0
    float4 ra = *reinterpret_cast<const float4*>(wp);
    float4 rb = *reinterpret_cast<const float4*>(xp);
    As[0][a_k4 + 0][a_m] = ra.x;
    As[0][a_k4 + 1][a_m] = ra.y;
    As[0][a_k4 + 2][a_m] = ra.z;
    As[0][a_k4 + 3][a_m] = ra.w;
    *reinterpret_cast<float4*>(&Bs[0][b_k][b_n4]) = rb;
    __syncthreads();

    const int T = Kd / KB;
    int buf = 0;
    for (int t = 0; t < T; t++) {
        if (t + 1 < T) {
            ra = *reinterpret_cast<const float4*>(wp + (t + 1) * KB);
            rb = *reinterpret_cast<const float4*>(xp + (size_t)(t + 1) * KB * NNE);
        }
        mma_tile(As[buf], Bs[buf], tx, ty, acc);
        if (t + 1 < T) {
            As[buf ^ 1][a_k4 + 0][a_m] = ra.x;
            As[buf ^ 1][a_k4 + 1][a_m] = ra.y;
            As[buf ^ 1][a_k4 + 2][a_m] = ra.z;
            As[buf ^ 1][a_k4 + 3][a_m] = ra.w;
            *reinterpret_cast<float4*>(&Bs[buf ^ 1][b_k][b_n4]) = rb;
        }
        __syncthreads();
        buf ^= 1;
    }

    // Epilogue
    const bool dobn = (op.gamma != nullptr);
#pragma unroll
    for (int i = 0; i < 8; i++) {
        const int mi = (i < 4) ? (ty * 4 + i) : (64 + ty * 4 + i - 4);
        const int m  = m0 + mi;
        const float bv = op.bias ? op.bias[m] : 0.f;
        float s = 1.f, h = 0.f;
        if (dobn) { s = op.gamma[m] * rsqrtf(1.f + 1e-5f); h = op.beta[m]; }
        const size_t rbase = (size_t)b * (size_t)Mtot * NNE + (size_t)m * NNE + n0;
#pragma unroll
        for (int j2 = 0; j2 < 4; j2++) {
            const int nj = (j2 < 2) ? (tx * 4 + j2 * 2) : (64 + tx * 4 + (j2 - 2) * 2);
            float y0, y1; unpack2(acc[i][j2], y0, y1);
            y0 += bv; y1 += bv;
            if (dobn) { y0 = fmaxf(y0 * s + h, 0.f); y1 = fmaxf(y1 * s + h, 0.f); }
            if (op.resid) { y0 += op.resid[rbase + nj]; y1 += op.resid[rbase + nj + 1]; }
            *reinterpret_cast<float2*>(&op.Y[rbase + nj]) = make_float2(y0, y1);
        }
    }
}

// ---------------------------------------------------------------------------
// S[sel][b][i][j] = scale * sum_k Q[sel][b][k][i] * Kf[b][k][j]
// Q = fvBase + sel*FSZ (fv then fh contiguous); S = Sbase + sel*SSZ.
// ---------------------------------------------------------------------------
__global__ __launch_bounds__(256, 2) void gemm_s(
    const float* __restrict__ fvBase, const float* __restrict__ fa,
    float* __restrict__ Sbase)
{
    const int z = blockIdx.z;
    const int b = z & 7, sel = z >> 3;
    const int j0 = blockIdx.x * TB;
    const int i0 = blockIdx.y * TB;
    const float* Qb = fvBase + (size_t)sel * FSZ + (size_t)b * MIDC * NNE;
    const float* Kb = fa + (size_t)b * MIDC * NNE;
    float* Sb = Sbase + (size_t)sel * SSZ + (size_t)b * (size_t)NNE * NNE;

    __shared__ float As[2][KB][TB];
    __shared__ float Bs[2][KB][TB];

    const int tid = threadIdx.x;
    const int tx = tid & 15, ty = tid >> 4;
    const int l_k = tid >> 5, l_n4 = (tid & 31) * 4;

    const float* qp = Qb + (size_t)l_k * NNE + i0 + l_n4;
    const float* kp = Kb + (size_t)l_k * NNE + j0 + l_n4;

    u64 acc[8][4];
#pragma unroll
    for (int i = 0; i < 8; i++)
#pragma unroll
        for (int j = 0; j < 4; j++) acc[i][j] = 0ull;

    float4 ra = *reinterpret_cast<const float4*>(qp);
    float4 rb = *reinterpret_cast<const float4*>(kp);
    *reinterpret_cast<float4*>(&As[0][l_k][l_n4]) = ra;
    *reinterpret_cast<float4*>(&Bs[0][l_k][l_n4]) = rb;
    __syncthreads();

    const int T = MIDC / KB;   // 16
    int buf = 0;
    for (int t = 0; t < T; t++) {
        if (t + 1 < T) {
            ra = *reinterpret_cast<const float4*>(qp + (size_t)(t + 1) * KB * NNE);
            rb = *reinterpret_cast<const float4*>(kp + (size_t)(t + 1) * KB * NNE);
        }
        mma_tile(As[buf], Bs[buf], tx, ty, acc);
        if (t + 1 < T) {
            *reinterpret_cast<float4*>(&As[buf ^ 1][l_k][l_n4]) = ra;
            *reinterpret_cast<float4*>(&Bs[buf ^ 1][l_k][l_n4]) = rb;
        }
        __syncthreads();
        buf ^= 1;
    }

    const float scale = 0.08838834764831845f;  // 128^-0.5
#pragma unroll
    for (int i = 0; i < 8; i++) {
        const int mi = (i < 4) ? (ty * 4 + i) : (64 + ty * 4 + i - 4);
        const size_t rbase = (size_t)(i0 + mi) * NNE + j0;
#pragma unroll
        for (int j2 = 0; j2 < 4; j2++) {
            const int nj = (j2 < 2) ? (tx * 4 + j2 * 2) : (64 + tx * 4 + (j2 - 2) * 2);
            float y0, y1; unpack2(acc[i][j2], y0, y1);
            *reinterpret_cast<float2*>(&Sb[rbase + nj]) = make_float2(y0 * scale, y1 * scale);
        }
    }
}

// ---------------------------------------------------------------------------
// In-place row softmax over last dim (rows of length 2304 = 9*256)
// ---------------------------------------------------------------------------
__global__ __launch_bounds__(256) void softmax_rows(float* __restrict__ S)
{
    float* p = S + (size_t)blockIdx.x * NNE;
    const int tid = threadIdx.x;

    float v[9];
    float mx = -3.4e38f;
#pragma unroll
    for (int i = 0; i < 9; i++) { v[i] = p[tid + i * 256]; mx = fmaxf(mx, v[i]); }

    __shared__ float sm[8];
#pragma unroll
    for (int o = 16; o > 0; o >>= 1) mx = fmaxf(mx, __shfl_xor_sync(0xffffffffu, mx, o));
    if ((tid & 31) == 0) sm[tid >> 5] = mx;
    __syncthreads();
    const float m2 = fmaxf(fmaxf(fmaxf(sm[0], sm[1]), fmaxf(sm[2], sm[3])),
                           fmaxf(fmaxf(sm[4], sm[5]), fmaxf(sm[6], sm[7])));

    float s = 0.f;
#pragma unroll
    for (int i = 0; i < 9; i++) { v[i] = __expf(v[i] - m2); s += v[i]; }
#pragma unroll
    for (int o = 16; o > 0; o >>= 1) s += __shfl_xor_sync(0xffffffffu, s, o);
    __syncthreads();
    if ((tid & 31) == 0) sm[tid >> 5] = s;
    __syncthreads();
    const float tot = sm[0] + sm[1] + sm[2] + sm[3] + sm[4] + sm[5] + sm[6] + sm[7];
    const float inv = __frcp_rn(tot);
#pragma unroll
    for (int i = 0; i < 9; i++) p[tid + i * 256] = v[i] * inv;
}

// ---------------------------------------------------------------------------
extern "C" void kernel_launch(void* const* d_in, const int* in_sizes, int n_in,
                              void* d_out, int out_size)
{
    (void)in_sizes; (void)n_in; (void)out_size;

    const float* x    = (const float*)d_in[0];
    const float* x_h  = (const float*)d_in[1];
    const float* x_v  = (const float*)d_in[2];
    const float* Wa   = (const float*)d_in[3];
    const float* ba   = (const float*)d_in[4];
    const float* ga   = (const float*)d_in[5];
    const float* ta   = (const float*)d_in[6];
    const float* Wv   = (const float*)d_in[7];
    const float* bv   = (const float*)d_in[8];
    const float* gv   = (const float*)d_in[9];
    const float* tv   = (const float*)d_in[10];
    const float* Wgav = (const float*)d_in[11];
    const float* bgav = (const float*)d_in[12];
    const float* Wgah = (const float*)d_in[13];
    const float* bgah = (const float*)d_in[14];
    const float* Wfav = (const float*)d_in[15];
    const float* bfav = (const float*)d_in[16];
    const float* Wfah = (const float*)d_in[17];
    const float* bfah = (const float*)d_in[18];

    void* sp = nullptr;
    cudaGetSymbolAddress(&sp, d_scratch);
    float* base = (float*)sp;
    float* fa  = base;
    float* fv  = base + FSZ;
    float* fh  = base + 2 * FSZ;
    float* gav = base + 3 * FSZ;
    float* gah = base + 4 * FSZ;
    float* oav = base + 5 * FSZ;
    float* oah = base + 6 * FSZ;
    float* Sav = base + 7 * FSZ;
    float* Sah = Sav + SSZ;

    float* out_h = (float*)d_out;
    float* out_v = out_h + (size_t)BB * CIN * NNE;

    dim3 blk(256);

    // 1) Five input 1x1 convs in one launch (720 blocks)
    GOps in5 = {};
    in5.v[0] = { Wa,   x,   ba,   ga,      ta,      nullptr, fa,  0 };
    in5.v[1] = { Wv,   x_v, bv,   gv,      tv,      nullptr, fv,  0 };
    in5.v[2] = { Wv,   x_h, bv,   gv,      tv,      nullptr, fh,  0 };
    in5.v[3] = { Wgav, x,   bgav, nullptr, nullptr, nullptr, gav, 0 };
    in5.v[4] = { Wgah, x,   bgah, nullptr, nullptr, nullptr, gah, 0 };
    gemm_multi<<<dim3(NNE / TB, 5, BB), blk>>>(in5, 1, CIN);

    // 2) Both attention-score GEMMs in one launch (5184 blocks)
    gemm_s<<<dim3(NNE / TB, NNE / TB, 2 * BB), blk>>>(fv, fa, Sav);

    // 3) Both softmaxes in one launch (Sav, Sah contiguous)
    softmax_rows<<<2 * BB * NNE, blk>>>(Sav);

    // 4) Both o = g @ A GEMMs in one launch (288 blocks)
    GOps o2 = {};
    o2.v[0] = { gav, Sav, nullptr, nullptr, nullptr, nullptr, oav, (size_t)MIDC * NNE };
    o2.v[1] = { gah, Sah, nullptr, nullptr, nullptr, nullptr, oah, (size_t)MIDC * NNE };
    gemm_multi<<<dim3(NNE / TB, 2, BB), blk>>>(o2, 1, NNE);

    // 5) Both output convs + residual in one launch (1152 blocks)
    GOps out2 = {};
    out2.v[0] = { Wfav, oav, bfav, nullptr, nullptr, x, out_v, 0 };
    out2.v[1] = { Wfah, oah, bfah, nullptr, nullptr, x, out_h, 0 };
    gemm_multi<<<dim3(NNE / TB, 2 * (CIN / TB), BB), blk>>>(out2, CIN / TB, MIDC);
}

// round 4
// speedup vs baseline: 1.7070x; 1.0008x over previous
#include <cuda_runtime.h>

typedef unsigned long long u64;

// Problem constants
#define BB   8
#define CIN  512
#define MIDC 128
#define NNE  2304   // H*W
#define TB   128
#define KB   8

#define FSZ  ((size_t)BB * MIDC * NNE)          // 2,359,296
#define SSZ  ((size_t)BB * NNE * NNE)           // 42,467,328
__device__ float d_scratch[7 * 2359296 + 2 * 42467328];

// ---------------------------------------------------------------------------
// f32x2 packed-FMA helpers
// ---------------------------------------------------------------------------
__device__ __forceinline__ u64 bcast2(float x) {
    u64 r; asm("mov.b64 %0, {%1, %1};" : "=l"(r) : "f"(x)); return r;
}
__device__ __forceinline__ void ffma2(u64& d, u64 a, u64 b) {
    asm("fma.rn.f32x2 %0, %1, %2, %3;" : "=l"(d) : "l"(a), "l"(b), "l"(d));
}
__device__ __forceinline__ void unpack2(u64 v, float& x, float& y) {
    asm("mov.b64 {%0, %1}, %2;" : "=f"(x), "=f"(y) : "l"(v));
}
__device__ __forceinline__ void lds2u64(u64& x, u64& y, const float* p) {
    unsigned a = (unsigned)__cvta_generic_to_shared(p);
    asm volatile("ld.shared.v2.b64 {%0, %1}, [%2];" : "=l"(x), "=l"(y) : "r"(a));
}

// ---------------------------------------------------------------------------
// Shared 128x128-tile microkernel step: one KB-deep smem tile -> acc update
// acc[i][j2]: i = m index (8), j2 = packed n pair (4) -> 8x8 outputs/thread
// ---------------------------------------------------------------------------
__device__ __forceinline__ void mma_tile(const float (*Ab)[TB], const float (*Bb)[TB],
                                         int tx, int ty, u64 acc[8][4])
{
#pragma unroll
    for (int k = 0; k < KB; k++) {
        float4 a0 = *reinterpret_cast<const float4*>(&Ab[k][ty * 4]);
        float4 a1 = *reinterpret_cast<const float4*>(&Ab[k][64 + ty * 4]);
        u64 b0, b1, b2, b3;
        lds2u64(b0, b1, &Bb[k][tx * 4]);
        lds2u64(b2, b3, &Bb[k][64 + tx * 4]);
        u64 av[8];
        av[0] = bcast2(a0.x); av[1] = bcast2(a0.y); av[2] = bcast2(a0.z); av[3] = bcast2(a0.w);
        av[4] = bcast2(a1.x); av[5] = bcast2(a1.y); av[6] = bcast2(a1.z); av[7] = bcast2(a1.w);
#pragma unroll
        for (int i = 0; i < 8; i++) {
            ffma2(acc[i][0], av[i], b0);
            ffma2(acc[i][1], av[i], b1);
            ffma2(acc[i][2], av[i], b2);
            ffma2(acc[i][3], av[i], b3);
        }
    }
}

// ---------------------------------------------------------------------------
// Multi-op GEMM: Y[b][m][n] = sum_k W[m][k] * X[b][k][n] (+bias)(+BN-ReLU)(+resid)
// Up to 5 ops per launch (same Kd / nMT across ops). blockIdx.y = op*nMT + mtile.
// ---------------------------------------------------------------------------
struct GOp {
    const float* W; const float* X;
    const float* bias; const float* gamma; const float* beta; const float* resid;
    float* Y; size_t wStride;
};
struct GOps { GOp v[5]; };

__global__ __launch_bounds__(256, 2) void gemm_multi(GOps ops, int nMT, int Kd)
{
    const int b  = blockIdx.z;
    const int n0 = blockIdx.x * TB;
    const int oi = blockIdx.y / nMT;
    const int m0 = (blockIdx.y % nMT) * TB;
    const GOp op = ops.v[oi];
    const int Mtot = nMT * TB;

    const float* W  = op.W + (size_t)b * op.wStride;
    const float* Xb = op.X + (size_t)b * (size_t)Kd * NNE;

    __shared__ float As[2][KB][TB];
    __shared__ float Bs[2][KB][TB];

    const int tid = threadIdx.x;
    const int tx = tid & 15, ty = tid >> 4;
    const int a_m = tid >> 1, a_k4 = (tid & 1) * 4;
    const int b_k = tid >> 5, b_n4 = (tid & 31) * 4;

    const float* wp = W  + (size_t)(m0 + a_m) * Kd + a_k4;
    const float* xp = Xb + (size_t)b_k * NNE + n0 + b_n4;

    u64 acc[8][4];
#pragma unroll
    for (int i = 0; i < 8; i++)
#pragma unroll
        for (int j = 0; j < 4; j++) acc[i][j] = 0ull;

    // Prologue: load tile 0
    float4 ra = *reinterpret_cast<const float4*>(wp);
    float4 rb = *reinterpret_cast<const float4*>(xp);
    As[0][a_k4 + 0][a_m] = ra.x;
    As[0][a_k4 + 1][a_m] = ra.y;
    As[0][a_k4 + 2][a_m] = ra.z;
    As[0][a_k4 + 3][a_m] = ra.w;
    *reinterpret_cast<float4*>(&Bs[0][b_k][b_n4]) = rb;
    __syncthreads();

    const int T = Kd / KB;
    int buf = 0;
    for (int t = 0; t < T; t++) {
        if (t + 1 < T) {
            ra = *reinterpret_cast<const float4*>(wp + (t + 1) * KB);
            rb = *reinterpret_cast<const float4*>(xp + (size_t)(t + 1) * KB * NNE);
        }
        mma_tile(As[buf], Bs[buf], tx, ty, acc);
        if (t + 1 < T) {
            As[buf ^ 1][a_k4 + 0][a_m] = ra.x;
            As[buf ^ 1][a_k4 + 1][a_m] = ra.y;
            As[buf ^ 1][a_k4 + 2][a_m] = ra.z;
            As[buf ^ 1][a_k4 + 3][a_m] = ra.w;
            *reinterpret_cast<float4*>(&Bs[buf ^ 1][b_k][b_n4]) = rb;
        }
        __syncthreads();
        buf ^= 1;
    }

    // Epilogue
    const bool dobn = (op.gamma != nullptr);
#pragma unroll
    for (int i = 0; i < 8; i++) {
        const int mi = (i < 4) ? (ty * 4 + i) : (64 + ty * 4 + i - 4);
        const int m  = m0 + mi;
        const float bv = op.bias ? op.bias[m] : 0.f;
        float s = 1.f, h = 0.f;
        if (dobn) { s = op.gamma[m] * rsqrtf(1.f + 1e-5f); h = op.beta[m]; }
        const size_t rbase = (size_t)b * (size_t)Mtot * NNE + (size_t)m * NNE + n0;
#pragma unroll
        for (int j2 = 0; j2 < 4; j2++) {
            const int nj = (j2 < 2) ? (tx * 4 + j2 * 2) : (64 + tx * 4 + (j2 - 2) * 2);
            float y0, y1; unpack2(acc[i][j2], y0, y1);
            y0 += bv; y1 += bv;
            if (dobn) { y0 = fmaxf(y0 * s + h, 0.f); y1 = fmaxf(y1 * s + h, 0.f); }
            if (op.resid) { y0 += op.resid[rbase + nj]; y1 += op.resid[rbase + nj + 1]; }
            *reinterpret_cast<float2*>(&op.Y[rbase + nj]) = make_float2(y0, y1);
        }
    }
}

// ---------------------------------------------------------------------------
// S[sel][b][i][j] = scale * sum_k Q[sel][b][k][i] * Kf[b][k][j]
// Q = fvBase + sel*FSZ (fv then fh contiguous); S = Sbase + sel*SSZ.
// ---------------------------------------------------------------------------
__global__ __launch_bounds__(256, 2) void gemm_s(
    const float* __restrict__ fvBase, const float* __restrict__ fa,
    float* __restrict__ Sbase)
{
    const int z = blockIdx.z;
    const int b = z & 7, sel = z >> 3;
    const int j0 = blockIdx.x * TB;
    const int i0 = blockIdx.y * TB;
    const float* Qb = fvBase + (size_t)sel * FSZ + (size_t)b * MIDC * NNE;
    const float* Kb = fa + (size_t)b * MIDC * NNE;
    float* Sb = Sbase + (size_t)sel * SSZ + (size_t)b * (size_t)NNE * NNE;

    __shared__ float As[2][KB][TB];
    __shared__ float Bs[2][KB][TB];

    const int tid = threadIdx.x;
    const int tx = tid & 15, ty = tid >> 4;
    const int l_k = tid >> 5, l_n4 = (tid & 31) * 4;

    const float* qp = Qb + (size_t)l_k * NNE + i0 + l_n4;
    const float* kp = Kb + (size_t)l_k * NNE + j0 + l_n4;

    u64 acc[8][4];
#pragma unroll
    for (int i = 0; i < 8; i++)
#pragma unroll
        for (int j = 0; j < 4; j++) acc[i][j] = 0ull;

    float4 ra = *reinterpret_cast<const float4*>(qp);
    float4 rb = *reinterpret_cast<const float4*>(kp);
    *reinterpret_cast<float4*>(&As[0][l_k][l_n4]) = ra;
    *reinterpret_cast<float4*>(&Bs[0][l_k][l_n4]) = rb;
    __syncthreads();

    const int T = MIDC / KB;   // 16
    int buf = 0;
    for (int t = 0; t < T; t++) {
        if (t + 1 < T) {
            ra = *reinterpret_cast<const float4*>(qp + (size_t)(t + 1) * KB * NNE);
            rb = *reinterpret_cast<const float4*>(kp + (size_t)(t + 1) * KB * NNE);
        }
        mma_tile(As[buf], Bs[buf], tx, ty, acc);
        if (t + 1 < T) {
            *reinterpret_cast<float4*>(&As[buf ^ 1][l_k][l_n4]) = ra;
            *reinterpret_cast<float4*>(&Bs[buf ^ 1][l_k][l_n4]) = rb;
        }
        __syncthreads();
        buf ^= 1;
    }

    const float scale = 0.08838834764831845f;  // 128^-0.5
#pragma unroll
    for (int i = 0; i < 8; i++) {
        const int mi = (i < 4) ? (ty * 4 + i) : (64 + ty * 4 + i - 4);
        const size_t rbase = (size_t)(i0 + mi) * NNE + j0;
#pragma unroll
        for (int j2 = 0; j2 < 4; j2++) {
            const int nj = (j2 < 2) ? (tx * 4 + j2 * 2) : (64 + tx * 4 + (j2 - 2) * 2);
            float y0, y1; unpack2(acc[i][j2], y0, y1);
            *reinterpret_cast<float2*>(&Sb[rbase + nj]) = make_float2(y0 * scale, y1 * scale);
        }
    }
}

// ---------------------------------------------------------------------------
// In-place row softmax over last dim (rows of length 2304 = 9*256)
// ---------------------------------------------------------------------------
__global__ __launch_bounds__(256) void softmax_rows(float* __restrict__ S)
{
    float* p = S + (size_t)blockIdx.x * NNE;
    const int tid = threadIdx.x;

    float v[9];
    float mx = -3.4e38f;
#pragma unroll
    for (int i = 0; i < 9; i++) { v[i] = p[tid + i * 256]; mx = fmaxf(mx, v[i]); }

    __shared__ float sm[8];
#pragma unroll
    for (int o = 16; o > 0; o >>= 1) mx = fmaxf(mx, __shfl_xor_sync(0xffffffffu, mx, o));
    if ((tid & 31) == 0) sm[tid >> 5] = mx;
    __syncthreads();
    const float m2 = fmaxf(fmaxf(fmaxf(sm[0], sm[1]), fmaxf(sm[2], sm[3])),
                           fmaxf(fmaxf(sm[4], sm[5]), fmaxf(sm[6], sm[7])));

    float s = 0.f;
#pragma unroll
    for (int i = 0; i < 9; i++) { v[i] = __expf(v[i] - m2); s += v[i]; }
#pragma unroll
    for (int o = 16; o > 0; o >>= 1) s += __shfl_xor_sync(0xffffffffu, s, o);
    __syncthreads();
    if ((tid & 31) == 0) sm[tid >> 5] = s;
    __syncthreads();
    const float tot = sm[0] + sm[1] + sm[2] + sm[3] + sm[4] + sm[5] + sm[6] + sm[7];
    const float inv = __frcp_rn(tot);
#pragma unroll
    for (int i = 0; i < 9; i++) p[tid + i * 256] = v[i] * inv;
}

// ---------------------------------------------------------------------------
extern "C" void kernel_launch(void* const* d_in, const int* in_sizes, int n_in,
                              void* d_out, int out_size)
{
    (void)in_sizes; (void)n_in; (void)out_size;

    const float* x    = (const float*)d_in[0];
    const float* x_h  = (const float*)d_in[1];
    const float* x_v  = (const float*)d_in[2];
    const float* Wa   = (const float*)d_in[3];
    const float* ba   = (const float*)d_in[4];
    const float* ga   = (const float*)d_in[5];
    const float* ta   = (const float*)d_in[6];
    const float* Wv   = (const float*)d_in[7];
    const float* bv   = (const float*)d_in[8];
    const float* gv   = (const float*)d_in[9];
    const float* tv   = (const float*)d_in[10];
    const float* Wgav = (const float*)d_in[11];
    const float* bgav = (const float*)d_in[12];
    const float* Wgah = (const float*)d_in[13];
    const float* bgah = (const float*)d_in[14];
    const float* Wfav = (const float*)d_in[15];
    const float* bfav = (const float*)d_in[16];
    const float* Wfah = (const float*)d_in[17];
    const float* bfah = (const float*)d_in[18];

    void* sp = nullptr;
    cudaGetSymbolAddress(&sp, d_scratch);
    float* base = (float*)sp;
    float* fa  = base;
    float* fv  = base + FSZ;
    float* fh  = base + 2 * FSZ;
    float* gav = base + 3 * FSZ;
    float* gah = base + 4 * FSZ;
    float* oav = base + 5 * FSZ;
    float* oah = base + 6 * FSZ;
    float* Sav = base + 7 * FSZ;
    float* Sah = Sav + SSZ;

    float* out_h = (float*)d_out;
    float* out_v = out_h + (size_t)BB * CIN * NNE;

    dim3 blk(256);

    // 1) Five input 1x1 convs in one launch (720 blocks)
    GOps in5 = {};
    in5.v[0] = { Wa,   x,   ba,   ga,      ta,      nullptr, fa,  0 };
    in5.v[1] = { Wv,   x_v, bv,   gv,      tv,      nullptr, fv,  0 };
    in5.v[2] = { Wv,   x_h, bv,   gv,      tv,      nullptr, fh,  0 };
    in5.v[3] = { Wgav, x,   bgav, nullptr, nullptr, nullptr, gav, 0 };
    in5.v[4] = { Wgah, x,   bgah, nullptr, nullptr, nullptr, gah, 0 };
    gemm_multi<<<dim3(NNE / TB, 5, BB), blk>>>(in5, 1, CIN);

    // 2) Both attention-score GEMMs in one launch (5184 blocks)
    gemm_s<<<dim3(NNE / TB, NNE / TB, 2 * BB), blk>>>(fv, fa, Sav);

    // 3) Both softmaxes in one launch (Sav, Sah contiguous)
    softmax_rows<<<2 * BB * NNE, blk>>>(Sav);

    // 4) Both o = g @ A GEMMs in one launch (288 blocks)
    GOps o2 = {};
    o2.v[0] = { gav, Sav, nullptr, nullptr, nullptr, nullptr, oav, (size_t)MIDC * NNE };
    o2.v[1] = { gah, Sah, nullptr, nullptr, nullptr, nullptr, oah, (size_t)MIDC * NNE };
    gemm_multi<<<dim3(NNE / TB, 2, BB), blk>>>(o2, 1, NNE);

    // 5) Both output convs + residual in one launch (1152 blocks)
    GOps out2 = {};
    out2.v[0] = { Wfav, oav, bfav, nullptr, nullptr, x, out_v, 0 };
    out2.v[1] = { Wfah, oah, bfah, nullptr, nullptr, x, out_h, 0 };
    gemm_multi<<<dim3(NNE / TB, 2 * (CIN / TB), BB), blk>>>(out2, CIN / TB, MIDC);
}

// round 6
// speedup vs baseline: 5.8109x; 3.4041x over previous
#include <cuda_runtime.h>
#include <cuda_bf16.h>
#include <cstdint>

typedef unsigned int u32;
typedef unsigned long long u64;

#define BB   8
#define CIN  512
#define MIDC 128
#define NNE  2304
#define SCALE_S 0.08838834764831845f

// ---------------- scratch layout (bytes) ----------------
#define XT_SZ   ((size_t)3*BB*NNE*CIN*2)       // xT,xvT,xhT bf16 [t][b][n][c]
#define FT_ONE  ((size_t)BB*NNE*MIDC*2)        // f_t bf16 [o][b][n][m]
#define G_SZ    ((size_t)2*BB*MIDC*NNE*4)      // g fp32 [sel][b][m][n]
#define GN_SZ   ((size_t)2*BB*MIDC*NNE*2)      // g/Z bf16
#define ET_SZ   ((size_t)2*BB*NNE*NNE*2)       // exp(S)^T bf16 [sel][b][j][i]
#define Z_SZ    ((size_t)2*BB*NNE*4)           // fp32 col sums
#define OT_SZ   ((size_t)2*BB*NNE*MIDC*2)      // oT bf16 [sel][b][j][m]
#define WC_SZ   ((size_t)6*65536*2)            // bf16 weights

#define XT_OFF  0ull
#define FT_OFF  (XT_OFF + XT_SZ)
#define G_OFF   (FT_OFF + 3*FT_ONE)
#define GN_OFF  (G_OFF + G_SZ)
#define ET_OFF  (GN_OFF + GN_SZ)
#define Z_OFF   (ET_OFF + ET_SZ)
#define OT_OFF  (Z_OFF + Z_SZ)
#define WC_OFF  (OT_OFF + OT_SZ)
#define TOTAL_SCRATCH (WC_OFF + WC_SZ)

__device__ __align__(1024) char d_scratch[TOTAL_SCRATCH];

// ---------------- HMMA building blocks (sm_80-class, no arch-a needed) ----------
__device__ __forceinline__ u32 pack_bf16(float lo, float hi) {
    u32 r; asm("cvt.rn.bf16x2.f32 %0, %1, %2;" : "=r"(r) : "f"(hi), "f"(lo)); return r;
}
__device__ __forceinline__ void cpasync16(u32 saddr, const void* g) {
    asm volatile("cp.async.cg.shared.global [%0], [%1], 16;" :: "r"(saddr), "l"(g));
}
#define CP_COMMIT() asm volatile("cp.async.commit_group;" ::: "memory")

__device__ __forceinline__ void ldsm_x4(u32 a, u32& r0, u32& r1, u32& r2, u32& r3) {
    asm volatile("ldmatrix.sync.aligned.m8n8.x4.shared.b16 {%0,%1,%2,%3}, [%4];"
                 : "=r"(r0), "=r"(r1), "=r"(r2), "=r"(r3) : "r"(a));
}
__device__ __forceinline__ void mma16816(float c[4], const u32 a[4], u32 b0, u32 b1) {
    asm volatile("mma.sync.aligned.m16n8k16.row.col.f32.bf16.bf16.f32 "
                 "{%0,%1,%2,%3}, {%4,%5,%6,%7}, {%8,%9}, {%0,%1,%2,%3};"
                 : "+f"(c[0]), "+f"(c[1]), "+f"(c[2]), "+f"(c[3])
                 : "r"(a[0]), "r"(a[1]), "r"(a[2]), "r"(a[3]), "r"(b0), "r"(b1));
}

// 128 rows x 32 bf16 tile (64B/row). Swizzled chunk (16B units) for conflict-free
// ldmatrix: cc = c ^ (r&3) ^ ((r>>2)&1)
__device__ __forceinline__ u32 sw_off(int r, int c) {
    int cc = c ^ (r & 3) ^ ((r >> 2) & 1);
    return (u32)(r * 64 + cc * 16);
}

#define TILE_BYTES 8192

__device__ __forceinline__ void tile_load(u32 sdst, const __nv_bfloat16* src,
                                          size_t pitch, int k0, int tid) {
    int r = tid >> 1;
    const char* g = (const char*)(src + (size_t)r * pitch + k0);
#pragma unroll
    for (int i = 0; i < 2; i++) {
        int c = (tid & 1) * 2 + i;
        cpasync16(sdst + sw_off(r, c), g + c * 16);
    }
}

// CTA 128x128 GEMM: acc[mf][nf][4] += A(128 x Kd, k-major) · B(128 x Kd, k-major)^T
// 256 threads, 8 warps in 2(M) x 4(N); warp tile 64x32.
__device__ __forceinline__ void hmma_gemm(
    u32 sA, u32 sB,
    const __nv_bfloat16* __restrict__ A, size_t pA,
    const __nv_bfloat16* __restrict__ B, size_t pB,
    int Kd, int tid, float acc[4][4][4])
{
#pragma unroll
    for (int i = 0; i < 4; i++)
#pragma unroll
        for (int j = 0; j < 4; j++)
#pragma unroll
            for (int e = 0; e < 4; e++) acc[i][j][e] = 0.f;

    const int lane = tid & 31, wid = tid >> 5;
    const int wm = wid & 1, wn = wid >> 1;

    tile_load(sA, A, pA, 0, tid);
    tile_load(sB, B, pB, 0, tid);
    CP_COMMIT();

    const int T = Kd >> 5;
    for (int t = 0; t < T; t++) {
        const int cur = t & 1;
        if (t + 1 < T) {
            tile_load(sA + (cur ^ 1) * TILE_BYTES, A, pA, (t + 1) * 32, tid);
            tile_load(sB + (cur ^ 1) * TILE_BYTES, B, pB, (t + 1) * 32, tid);
            CP_COMMIT();
            asm volatile("cp.async.wait_group 1;" ::: "memory");
        } else {
            asm volatile("cp.async.wait_group 0;" ::: "memory");
        }
        __syncthreads();
        const u32 abuf = sA + cur * TILE_BYTES;
        const u32 bbuf = sB + cur * TILE_BYTES;
#pragma unroll
        for (int k16 = 0; k16 < 2; k16++) {
            u32 a[4][4];
#pragma unroll
            for (int f = 0; f < 4; f++) {
                int row = wm * 64 + f * 16 + (lane & 15);
                int ch  = k16 * 2 + (lane >> 4);
                ldsm_x4(abuf + sw_off(row, ch), a[f][0], a[f][1], a[f][2], a[f][3]);
            }
            u32 b[4][2];
#pragma unroll
            for (int p = 0; p < 2; p++) {
                int row = wn * 32 + p * 16 + ((lane & 16) >> 1) + (lane & 7);
                int ch  = k16 * 2 + ((lane >> 3) & 1);
                ldsm_x4(bbuf + sw_off(row, ch), b[2 * p][0], b[2 * p][1],
                        b[2 * p + 1][0], b[2 * p + 1][1]);
            }
#pragma unroll
            for (int mf = 0; mf < 4; mf++)
#pragma unroll
                for (int nf = 0; nf < 4; nf++)
                    mma16816(acc[mf][nf], a[mf], b[nf][0], b[nf][1]);
        }
        __syncthreads();
    }
}

struct SmemTiles { char A[2][TILE_BYTES]; char B[2][TILE_BYTES]; };

// ============================ SIMT prep ============================
__global__ __launch_bounds__(256) void transpose_x(
    const float* __restrict__ x, const float* __restrict__ x_v,
    const float* __restrict__ x_h, __nv_bfloat16* __restrict__ xT)
{
    __shared__ float t[32][33];
    int z = blockIdx.z, tt = z >> 3, b = z & 7;
    const float* src = (tt == 0) ? x : (tt == 1 ? x_v : x_h);
    int n0 = blockIdx.x * 32, c0 = blockIdx.y * 32;
    int tx = threadIdx.x & 31, ty8 = threadIdx.x >> 5;
#pragma unroll
    for (int i = 0; i < 4; i++)
        t[ty8 + i * 8][tx] = src[((size_t)b * CIN + c0 + ty8 + i * 8) * NNE + n0 + tx];
    __syncthreads();
#pragma unroll
    for (int i = 0; i < 4; i++)
        xT[(((size_t)tt * BB + b) * NNE + n0 + ty8 + i * 8) * CIN + c0 + tx] =
            __float2bfloat16(t[tx][ty8 + i * 8]);
}

struct WC6 { const float* s[6]; };
__global__ __launch_bounds__(256) void conv_weights(WC6 w, __nv_bfloat16* __restrict__ dst,
                                                    float* __restrict__ Z)
{
    int idx = blockIdx.x * 256 + threadIdx.x;          // 6*65536 threads
    int t = idx >> 16, i = idx & 65535;
    dst[(size_t)t * 65536 + i] = __float2bfloat16(w.s[t][i]);
    if (idx < 2 * BB * NNE) Z[idx] = 0.f;
}

__global__ __launch_bounds__(256) void gnorm(
    const float* __restrict__ g, const float* __restrict__ Z, __nv_bfloat16* __restrict__ gn)
{
    size_t idx = (size_t)blockIdx.x * 256 + threadIdx.x;
    int n = (int)(idx % NNE);
    size_t sb = idx / ((size_t)NNE * MIDC);
    gn[idx] = __float2bfloat16(g[idx] * __frcp_rn(Z[sb * NNE + n]));
}

// ============================ HMMA kernels ============================

// f[o][b][n][m] = relu(BN(xT·W^T)). grid (18, BB, 3). rows=n, cols=m.
__global__ __launch_bounds__(256, 2) void k_fconv(
    const __nv_bfloat16* __restrict__ xT, const __nv_bfloat16* __restrict__ Wc,
    const float* __restrict__ ba, const float* __restrict__ ga, const float* __restrict__ ta,
    const float* __restrict__ bv, const float* __restrict__ gv, const float* __restrict__ tv,
    __nv_bfloat16* __restrict__ ft)
{
    __shared__ SmemTiles st;
    __shared__ float sS[128], sC[128];
    int tid = threadIdx.x, lane = tid & 31, wid = tid >> 5;
    int wm = wid & 1, wn = wid >> 1;
    int nt = blockIdx.x, b = blockIdx.y, o = blockIdx.z;

    if (tid < 128) {
        const float* bias  = (o == 0) ? ba : bv;
        const float* gamma = (o == 0) ? ga : gv;
        const float* beta  = (o == 0) ? ta : tv;
        float s = gamma[tid] * rsqrtf(1.f + 1e-5f);
        sS[tid] = s; sC[tid] = bias[tid] * s + beta[tid];
    }

    const __nv_bfloat16* A = xT + (((size_t)o * BB + b) * NNE + (size_t)nt * 128) * CIN;
    const __nv_bfloat16* B = Wc + (size_t)((o == 0) ? 0 : 1) * 65536;

    float acc[4][4][4];
    u32 sA = (u32)__cvta_generic_to_shared(st.A);
    u32 sB = (u32)__cvta_generic_to_shared(st.B);
    hmma_gemm(sA, sB, A, CIN, B, CIN, CIN, tid, acc);

    __nv_bfloat16* dst = ft + (size_t)o * (size_t)BB * NNE * MIDC
                            + ((size_t)b * NNE + (size_t)nt * 128) * MIDC;
#pragma unroll
    for (int mf = 0; mf < 4; mf++)
#pragma unroll
        for (int nf = 0; nf < 4; nf++)
#pragma unroll
            for (int h = 0; h < 2; h++) {
                int r = wm * 64 + mf * 16 + (lane >> 2) + h * 8;
                int c = wn * 32 + nf * 8 + ((lane & 3) << 1);
                float y0 = fmaxf(acc[mf][nf][h * 2]     * sS[c]     + sC[c],     0.f);
                float y1 = fmaxf(acc[mf][nf][h * 2 + 1] * sS[c + 1] + sC[c + 1], 0.f);
                *reinterpret_cast<u32*>(dst + (size_t)r * MIDC + c) = pack_bf16(y0, y1);
            }
}

// g[sel][b][m][n] = Wg·xT^T + bias (fp32). grid (18, BB, 2). rows=m, cols=n.
__global__ __launch_bounds__(256, 2) void k_gconv(
    const __nv_bfloat16* __restrict__ xT, const __nv_bfloat16* __restrict__ Wc,
    const float* __restrict__ bgav, const float* __restrict__ bgah,
    float* __restrict__ g)
{
    __shared__ SmemTiles st;
    int tid = threadIdx.x, lane = tid & 31, wid = tid >> 5;
    int wm = wid & 1, wn = wid >> 1;
    int nt = blockIdx.x, b = blockIdx.y, o = blockIdx.z;

    const __nv_bfloat16* A = Wc + (size_t)(2 + o) * 65536;
    const __nv_bfloat16* B = xT + ((size_t)b * NNE + (size_t)nt * 128) * CIN;

    float acc[4][4][4];
    u32 sA = (u32)__cvta_generic_to_shared(st.A);
    u32 sB = (u32)__cvta_generic_to_shared(st.B);
    hmma_gemm(sA, sB, A, CIN, B, CIN, CIN, tid, acc);

    const float* bias = (o == 0) ? bgav : bgah;
    float* dst = g + (size_t)(o * BB + b) * MIDC * NNE + (size_t)nt * 128;
#pragma unroll
    for (int mf = 0; mf < 4; mf++)
#pragma unroll
        for (int nf = 0; nf < 4; nf++)
#pragma unroll
            for (int h = 0; h < 2; h++) {
                int r = wm * 64 + mf * 16 + (lane >> 2) + h * 8;
                int c = wn * 32 + nf * 8 + ((lane & 3) << 1);
                float bval = bias[r];
                *reinterpret_cast<float2*>(dst + (size_t)r * NNE + c) =
                    make_float2(acc[mf][nf][h * 2] + bval, acc[mf][nf][h * 2 + 1] + bval);
            }
}

// ET[sel][b][j][i] = exp(scale * fa[j]·fq[i]); Z[sel][b][i] += column sums.
// grid (it 18, jt 18, b + 8*sel). rows=j, cols=i.
__global__ __launch_bounds__(256, 2) void k_score(
    const __nv_bfloat16* __restrict__ ft, __nv_bfloat16* __restrict__ et,
    float* __restrict__ Z)
{
    __shared__ SmemTiles st;
    __shared__ float zs[2][128];
    int tid = threadIdx.x, lane = tid & 31, wid = tid >> 5;
    int wm = wid & 1, wn = wid >> 1;
    int it = blockIdx.x, jt = blockIdx.y;
    int z = blockIdx.z, b = z & 7, sel = z >> 3;

    const __nv_bfloat16* fa = ft + (size_t)b * NNE * MIDC;
    const __nv_bfloat16* fq = ft + (size_t)(1 + sel) * (size_t)BB * NNE * MIDC
                                 + (size_t)b * NNE * MIDC;
    const __nv_bfloat16* A = fa + (size_t)jt * 128 * MIDC;
    const __nv_bfloat16* B = fq + (size_t)it * 128 * MIDC;

    float acc[4][4][4];
    u32 sA = (u32)__cvta_generic_to_shared(st.A);
    u32 sB = (u32)__cvta_generic_to_shared(st.B);
    hmma_gemm(sA, sB, A, MIDC, B, MIDC, MIDC, tid, acc);

    // exp in place
#pragma unroll
    for (int mf = 0; mf < 4; mf++)
#pragma unroll
        for (int nf = 0; nf < 4; nf++)
#pragma unroll
            for (int e = 0; e < 4; e++)
                acc[mf][nf][e] = __expf(acc[mf][nf][e] * SCALE_S);

    __nv_bfloat16* dst = et + ((size_t)(sel * BB + b) * NNE + (size_t)jt * 128) * NNE
                            + (size_t)it * 128;
#pragma unroll
    for (int mf = 0; mf < 4; mf++)
#pragma unroll
        for (int nf = 0; nf < 4; nf++)
#pragma unroll
            for (int h = 0; h < 2; h++) {
                int r = wm * 64 + mf * 16 + (lane >> 2) + h * 8;
                int c = wn * 32 + nf * 8 + ((lane & 3) << 1);
                *reinterpret_cast<u32*>(dst + (size_t)r * NNE + c) =
                    pack_bf16(acc[mf][nf][h * 2], acc[mf][nf][h * 2 + 1]);
            }

    // column sums within CTA: reduce over rows (mf,h) then across lane>>2
#pragma unroll
    for (int nf = 0; nf < 4; nf++) {
        float s0 = 0.f, s1 = 0.f;
#pragma unroll
        for (int mf = 0; mf < 4; mf++) {
            s0 += acc[mf][nf][0] + acc[mf][nf][2];
            s1 += acc[mf][nf][1] + acc[mf][nf][3];
        }
#pragma unroll
        for (int off = 4; off < 32; off <<= 1) {
            s0 += __shfl_xor_sync(0xffffffffu, s0, off);
            s1 += __shfl_xor_sync(0xffffffffu, s1, off);
        }
        if (lane < 4) {
            int c = wn * 32 + nf * 8 + lane * 2;
            zs[wm][c] = s0;
            zs[wm][c + 1] = s1;
        }
    }
    __syncthreads();
    if (tid < 128)
        atomicAdd(&Z[(size_t)(sel * BB + b) * NNE + (size_t)it * 128 + tid],
                  zs[0][tid] + zs[1][tid]);
}

// oT[sel][b][j][m] = sum_i ET[j][i]·gn[m][i]. grid (jt 18, 1, b+8*sel). rows=j, cols=m.
__global__ __launch_bounds__(256, 2) void k_ogemm(
    const __nv_bfloat16* __restrict__ et, const __nv_bfloat16* __restrict__ gn,
    __nv_bfloat16* __restrict__ oT)
{
    __shared__ SmemTiles st;
    int tid = threadIdx.x, lane = tid & 31, wid = tid >> 5;
    int wm = wid & 1, wn = wid >> 1;
    int jt = blockIdx.x;
    int z = blockIdx.z, b = z & 7, sel = z >> 3;

    const __nv_bfloat16* A = et + ((size_t)(sel * BB + b) * NNE + (size_t)jt * 128) * NNE;
    const __nv_bfloat16* B = gn + (size_t)(sel * BB + b) * MIDC * NNE;

    float acc[4][4][4];
    u32 sA = (u32)__cvta_generic_to_shared(st.A);
    u32 sB = (u32)__cvta_generic_to_shared(st.B);
    hmma_gemm(sA, sB, A, NNE, B, NNE, NNE, tid, acc);

    __nv_bfloat16* dst = oT + ((size_t)(sel * BB + b) * NNE + (size_t)jt * 128) * MIDC;
#pragma unroll
    for (int mf = 0; mf < 4; mf++)
#pragma unroll
        for (int nf = 0; nf < 4; nf++)
#pragma unroll
            for (int h = 0; h < 2; h++) {
                int r = wm * 64 + mf * 16 + (lane >> 2) + h * 8;
                int c = wn * 32 + nf * 8 + ((lane & 3) << 1);
                *reinterpret_cast<u32*>(dst + (size_t)r * MIDC + c) =
                    pack_bf16(acc[mf][nf][h * 2], acc[mf][nf][h * 2 + 1]);
            }
}

// out[sel][b][cout][n] = Wf·oT^T + bias + x. grid (nt 18, ct 4, b+8*sel). rows=cout, cols=n.
__global__ __launch_bounds__(256, 2) void k_outconv(
    const __nv_bfloat16* __restrict__ Wc, const __nv_bfloat16* __restrict__ oT,
    const float* __restrict__ bfav, const float* __restrict__ bfah,
    const float* __restrict__ x,
    float* __restrict__ out_v, float* __restrict__ out_h)
{
    __shared__ SmemTiles st;
    int tid = threadIdx.x, lane = tid & 31, wid = tid >> 5;
    int wm = wid & 1, wn = wid >> 1;
    int nt = blockIdx.x, ct = blockIdx.y;
    int z = blockIdx.z, b = z & 7, sel = z >> 3;

    const __nv_bfloat16* A = Wc + (size_t)(4 + sel) * 65536 + (size_t)ct * 128 * MIDC;
    const __nv_bfloat16* B = oT + ((size_t)(sel * BB + b) * NNE + (size_t)nt * 128) * MIDC;

    float acc[4][4][4];
    u32 sA = (u32)__cvta_generic_to_shared(st.A);
    u32 sB = (u32)__cvta_generic_to_shared(st.B);
    hmma_gemm(sA, sB, A, MIDC, B, MIDC, MIDC, tid, acc);

    const float* bias = (sel == 0) ? bfav : bfah;
    float* outp = (sel == 0) ? out_v : out_h;
#pragma unroll
    for (int mf = 0; mf < 4; mf++)
#pragma unroll
        for (int nf = 0; nf < 4; nf++)
#pragma unroll
            for (int h = 0; h < 2; h++) {
                int r = wm * 64 + mf * 16 + (lane >> 2) + h * 8;
                int c = wn * 32 + nf * 8 + ((lane & 3) << 1);
                int cout = ct * 128 + r;
                size_t base = ((size_t)b * CIN + cout) * NNE + (size_t)nt * 128 + c;
                float2 xv = *reinterpret_cast<const float2*>(x + base);
                float bval = bias[cout];
                *reinterpret_cast<float2*>(outp + base) =
                    make_float2(acc[mf][nf][h * 2] + bval + xv.x,
                                acc[mf][nf][h * 2 + 1] + bval + xv.y);
            }
}

// ============================================================================
extern "C" void kernel_launch(void* const* d_in, const int* in_sizes, int n_in,
                              void* d_out, int out_size)
{
    (void)in_sizes; (void)n_in; (void)out_size;

    const float* x    = (const float*)d_in[0];
    const float* x_h  = (const float*)d_in[1];
    const float* x_v  = (const float*)d_in[2];
    const float* Wa   = (const float*)d_in[3];
    const float* ba   = (const float*)d_in[4];
    const float* ga   = (const float*)d_in[5];
    const float* ta   = (const float*)d_in[6];
    const float* Wv   = (const float*)d_in[7];
    const float* bv   = (const float*)d_in[8];
    const float* gv   = (const float*)d_in[9];
    const float* tv   = (const float*)d_in[10];
    const float* Wgav = (const float*)d_in[11];
    const float* bgav = (const float*)d_in[12];
    const float* Wgah = (const float*)d_in[13];
    const float* bgah = (const float*)d_in[14];
    const float* Wfav = (const float*)d_in[15];
    const float* bfav = (const float*)d_in[16];
    const float* Wfah = (const float*)d_in[17];
    const float* bfah = (const float*)d_in[18];

    void* sp = nullptr;
    cudaGetSymbolAddress(&sp, d_scratch);
    char* base = (char*)sp;
    __nv_bfloat16* xT = (__nv_bfloat16*)(base + XT_OFF);
    __nv_bfloat16* ft = (__nv_bfloat16*)(base + FT_OFF);
    float*         g  = (float*)(base + G_OFF);
    __nv_bfloat16* gn = (__nv_bfloat16*)(base + GN_OFF);
    __nv_bfloat16* et = (__nv_bfloat16*)(base + ET_OFF);
    float*         Zp = (float*)(base + Z_OFF);
    __nv_bfloat16* oT = (__nv_bfloat16*)(base + OT_OFF);
    __nv_bfloat16* Wc = (__nv_bfloat16*)(base + WC_OFF);

    float* out_h = (float*)d_out;
    float* out_v = out_h + (size_t)BB * CIN * NNE;

    // prep: transpose x to bf16 [n][c]; weights to bf16; zero Z
    transpose_x<<<dim3(NNE / 32, CIN / 32, 3 * BB), 256>>>(x, x_v, x_h, xT);
    WC6 w = {{ Wa, Wv, Wgav, Wgah, Wfav, Wfah }};
    conv_weights<<<1536, 256>>>(w, Wc, Zp);

    // input convs
    k_fconv<<<dim3(18, BB, 3), 256>>>(xT, Wc, ba, ga, ta, bv, gv, tv, ft);
    k_gconv<<<dim3(18, BB, 2), 256>>>(xT, Wc, bgav, bgah, g);

    // scores: ET = exp(scale*S)^T, Z = per-query sums
    k_score<<<dim3(18, 18, 16), 256>>>(ft, et, Zp);

    // fold 1/Z into g
    gnorm<<<(2 * BB * MIDC * NNE) / 256, 256>>>(g, Zp, gn);

    // oT = ET·gn^T
    k_ogemm<<<dim3(18, 1, 16), 256>>>(et, gn, oT);

    // output convs + residual
    k_outconv<<<dim3(18, 4, 16), 256>>>(Wc, oT, bfav, bfah, x, out_v, out_h);
}

// round 7
// speedup vs baseline: 5.8182x; 1.0013x over previous
#include <cuda_runtime.h>
#include <cuda_bf16.h>
#include <cstdint>

typedef unsigned int u32;
typedef unsigned long long u64;

#define BB   8
#define CIN  512
#define MIDC 128
#define NNE  2304
#define SCALE_S 0.08838834764831845f

// ---------------- scratch layout (bytes) ----------------
#define XT_SZ   ((size_t)3*BB*NNE*CIN*2)       // xT,xvT,xhT bf16 [t][b][n][c]
#define FT_ONE  ((size_t)BB*NNE*MIDC*2)        // f_t bf16 [o][b][n][m]
#define G_SZ    ((size_t)2*BB*MIDC*NNE*4)      // g fp32 [sel][b][m][n]
#define GN_SZ   ((size_t)2*BB*MIDC*NNE*2)      // g/Z bf16
#define ET_SZ   ((size_t)2*BB*NNE*NNE*2)       // exp(S)^T bf16 [sel][b][j][i]
#define Z_SZ    ((size_t)2*BB*NNE*4)           // fp32 col sums
#define OT_SZ   ((size_t)2*BB*NNE*MIDC*2)      // oT bf16 [sel][b][j][m]
#define WC_SZ   ((size_t)6*65536*2)            // bf16 weights

#define XT_OFF  0ull
#define FT_OFF  (XT_OFF + XT_SZ)
#define G_OFF   (FT_OFF + 3*FT_ONE)
#define GN_OFF  (G_OFF + G_SZ)
#define ET_OFF  (GN_OFF + GN_SZ)
#define Z_OFF   (ET_OFF + ET_SZ)
#define OT_OFF  (Z_OFF + Z_SZ)
#define WC_OFF  (OT_OFF + OT_SZ)
#define TOTAL_SCRATCH (WC_OFF + WC_SZ)

__device__ __align__(1024) char d_scratch[TOTAL_SCRATCH];

// ---------------- HMMA building blocks ----------------
__device__ __forceinline__ u32 pack_bf16(float lo, float hi) {
    u32 r; asm("cvt.rn.bf16x2.f32 %0, %1, %2;" : "=r"(r) : "f"(hi), "f"(lo)); return r;
}
__device__ __forceinline__ void cpasync16(u32 saddr, const void* g) {
    asm volatile("cp.async.cg.shared.global [%0], [%1], 16;" :: "r"(saddr), "l"(g));
}
#define CP_COMMIT() asm volatile("cp.async.commit_group;" ::: "memory")

__device__ __forceinline__ void ldsm_x4(u32 a, u32& r0, u32& r1, u32& r2, u32& r3) {
    asm volatile("ldmatrix.sync.aligned.m8n8.x4.shared.b16 {%0,%1,%2,%3}, [%4];"
                 : "=r"(r0), "=r"(r1), "=r"(r2), "=r"(r3) : "r"(a));
}
__device__ __forceinline__ void mma16816(float c[4], const u32 a[4], u32 b0, u32 b1) {
    asm volatile("mma.sync.aligned.m16n8k16.row.col.f32.bf16.bf16.f32 "
                 "{%0,%1,%2,%3}, {%4,%5,%6,%7}, {%8,%9}, {%0,%1,%2,%3};"
                 : "+f"(c[0]), "+f"(c[1]), "+f"(c[2]), "+f"(c[3])
                 : "r"(a[0]), "r"(a[1]), "r"(a[2]), "r"(a[3]), "r"(b0), "r"(b1));
}

// Tile: 128 rows x 64 bf16 (128 B/row), 8 x 16B chunks per row.
// Swizzle cc = c ^ (r & 7): conflict-free for cp.async stores and ldmatrix reads.
#define BK 64
#define TILE_B (128 * BK * 2)   // 16384 bytes

__device__ __forceinline__ u32 sw64(int r, int ch) {
    return (u32)(r * 128 + ((ch ^ (r & 7)) << 4));
}

__device__ __forceinline__ void tile_load(u32 sdst, const __nv_bfloat16* src,
                                          size_t pitch, int k0, int tid) {
    int r = tid >> 1;
    const char* g = (const char*)(src + (size_t)r * pitch + k0);
#pragma unroll
    for (int i = 0; i < 4; i++) {
        int c = (tid & 1) * 4 + i;
        cpasync16(sdst + sw64(r, c), g + c * 16);
    }
}

// CTA 128x128 GEMM: acc += A(128 x Kd, k-major) · B(128 x Kd, k-major)^T
// 256 threads, 8 warps 2(M) x 4(N), warp tile 64x32, BK=64 double-buffered.
__device__ __forceinline__ void hmma_gemm(
    u32 sA, u32 sB,
    const __nv_bfloat16* __restrict__ A, size_t pA,
    const __nv_bfloat16* __restrict__ B, size_t pB,
    int Kd, int tid, float acc[4][4][4])
{
#pragma unroll
    for (int i = 0; i < 4; i++)
#pragma unroll
        for (int j = 0; j < 4; j++)
#pragma unroll
            for (int e = 0; e < 4; e++) acc[i][j][e] = 0.f;

    const int lane = tid & 31, wid = tid >> 5;
    const int wm = wid & 1, wn = wid >> 1;

    tile_load(sA, A, pA, 0, tid);
    tile_load(sB, B, pB, 0, tid);
    CP_COMMIT();

    const int T = Kd / BK;
    for (int t = 0; t < T; t++) {
        const int cur = t & 1;
        if (t + 1 < T) {
            tile_load(sA + (cur ^ 1) * TILE_B, A, pA, (t + 1) * BK, tid);
            tile_load(sB + (cur ^ 1) * TILE_B, B, pB, (t + 1) * BK, tid);
            CP_COMMIT();
            asm volatile("cp.async.wait_group 1;" ::: "memory");
        } else {
            asm volatile("cp.async.wait_group 0;" ::: "memory");
        }
        __syncthreads();
        const u32 abuf = sA + cur * TILE_B;
        const u32 bbuf = sB + cur * TILE_B;
#pragma unroll
        for (int k16 = 0; k16 < 4; k16++) {
            u32 a[4][4];
#pragma unroll
            for (int f = 0; f < 4; f++) {
                int row = wm * 64 + f * 16 + (lane & 15);
                int ch  = k16 * 2 + (lane >> 4);
                ldsm_x4(abuf + sw64(row, ch), a[f][0], a[f][1], a[f][2], a[f][3]);
            }
            u32 b[4][2];
#pragma unroll
            for (int p = 0; p < 2; p++) {
                int row = wn * 32 + p * 16 + ((lane & 16) >> 1) + (lane & 7);
                int ch  = k16 * 2 + ((lane >> 3) & 1);
                ldsm_x4(bbuf + sw64(row, ch), b[2 * p][0], b[2 * p][1],
                        b[2 * p + 1][0], b[2 * p + 1][1]);
            }
#pragma unroll
            for (int mf = 0; mf < 4; mf++)
#pragma unroll
                for (int nf = 0; nf < 4; nf++)
                    mma16816(acc[mf][nf], a[mf], b[nf][0], b[nf][1]);
        }
        __syncthreads();
    }
}

#define SMEM_DYN (4 * TILE_B)   // A0,A1,B0,B1 = 64 KB

// ============================ SIMT prep ============================
__global__ __launch_bounds__(256) void transpose_x(
    const float* __restrict__ x, const float* __restrict__ x_v,
    const float* __restrict__ x_h, __nv_bfloat16* __restrict__ xT)
{
    __shared__ float t[32][33];
    int z = blockIdx.z, tt = z >> 3, b = z & 7;
    const float* src = (tt == 0) ? x : (tt == 1 ? x_v : x_h);
    int n0 = blockIdx.x * 32, c0 = blockIdx.y * 32;
    int tx = threadIdx.x & 31, ty8 = threadIdx.x >> 5;
#pragma unroll
    for (int i = 0; i < 4; i++)
        t[ty8 + i * 8][tx] = src[((size_t)b * CIN + c0 + ty8 + i * 8) * NNE + n0 + tx];
    __syncthreads();
#pragma unroll
    for (int i = 0; i < 4; i++)
        xT[(((size_t)tt * BB + b) * NNE + n0 + ty8 + i * 8) * CIN + c0 + tx] =
            __float2bfloat16(t[tx][ty8 + i * 8]);
}

struct WC6 { const float* s[6]; };
__global__ __launch_bounds__(256) void conv_weights(WC6 w, __nv_bfloat16* __restrict__ dst,
                                                    float* __restrict__ Z)
{
    int idx = blockIdx.x * 256 + threadIdx.x;
    int t = idx >> 16, i = idx & 65535;
    dst[(size_t)t * 65536 + i] = __float2bfloat16(w.s[t][i]);
    if (idx < 2 * BB * NNE) Z[idx] = 0.f;
}

__global__ __launch_bounds__(256) void gnorm(
    const float* __restrict__ g, const float* __restrict__ Z, __nv_bfloat16* __restrict__ gn)
{
    size_t idx = (size_t)blockIdx.x * 256 + threadIdx.x;
    int n = (int)(idx % NNE);
    size_t sb = idx / ((size_t)NNE * MIDC);
    gn[idx] = __float2bfloat16(g[idx] * __frcp_rn(Z[sb * NNE + n]));
}

// ============================ HMMA kernels ============================

// f[o][b][n][m] = relu(BN(xT·W^T)). grid (18, BB, 3). rows=n, cols=m.
__global__ __launch_bounds__(256, 2) void k_fconv(
    const __nv_bfloat16* __restrict__ xT, const __nv_bfloat16* __restrict__ Wc,
    const float* __restrict__ ba, const float* __restrict__ ga, const float* __restrict__ ta,
    const float* __restrict__ bv, const float* __restrict__ gv, const float* __restrict__ tv,
    __nv_bfloat16* __restrict__ ft)
{
    extern __shared__ char dsm[];
    __shared__ float sS[128], sC[128];
    int tid = threadIdx.x, lane = tid & 31, wid = tid >> 5;
    int wm = wid & 1, wn = wid >> 1;
    int nt = blockIdx.x, b = blockIdx.y, o = blockIdx.z;

    if (tid < 128) {
        const float* bias  = (o == 0) ? ba : bv;
        const float* gamma = (o == 0) ? ga : gv;
        const float* beta  = (o == 0) ? ta : tv;
        float s = gamma[tid] * rsqrtf(1.f + 1e-5f);
        sS[tid] = s; sC[tid] = bias[tid] * s + beta[tid];
    }

    const __nv_bfloat16* A = xT + (((size_t)o * BB + b) * NNE + (size_t)nt * 128) * CIN;
    const __nv_bfloat16* B = Wc + (size_t)((o == 0) ? 0 : 1) * 65536;

    float acc[4][4][4];
    u32 sA = (u32)__cvta_generic_to_shared(dsm);
    u32 sB = sA + 2 * TILE_B;
    hmma_gemm(sA, sB, A, CIN, B, CIN, CIN, tid, acc);

    __nv_bfloat16* dst = ft + (size_t)o * (size_t)BB * NNE * MIDC
                            + ((size_t)b * NNE + (size_t)nt * 128) * MIDC;
#pragma unroll
    for (int mf = 0; mf < 4; mf++)
#pragma unroll
        for (int nf = 0; nf < 4; nf++)
#pragma unroll
            for (int h = 0; h < 2; h++) {
                int r = wm * 64 + mf * 16 + (lane >> 2) + h * 8;
                int c = wn * 32 + nf * 8 + ((lane & 3) << 1);
                float y0 = fmaxf(acc[mf][nf][h * 2]     * sS[c]     + sC[c],     0.f);
                float y1 = fmaxf(acc[mf][nf][h * 2 + 1] * sS[c + 1] + sC[c + 1], 0.f);
                *reinterpret_cast<u32*>(dst + (size_t)r * MIDC + c) = pack_bf16(y0, y1);
            }
}

// g[sel][b][m][n] = Wg·xT^T + bias (fp32). grid (18, BB, 2). rows=m, cols=n.
__global__ __launch_bounds__(256, 2) void k_gconv(
    const __nv_bfloat16* __restrict__ xT, const __nv_bfloat16* __restrict__ Wc,
    const float* __restrict__ bgav, const float* __restrict__ bgah,
    float* __restrict__ g)
{
    extern __shared__ char dsm[];
    int tid = threadIdx.x, lane = tid & 31, wid = tid >> 5;
    int wm = wid & 1, wn = wid >> 1;
    int nt = blockIdx.x, b = blockIdx.y, o = blockIdx.z;

    const __nv_bfloat16* A = Wc + (size_t)(2 + o) * 65536;
    const __nv_bfloat16* B = xT + ((size_t)b * NNE + (size_t)nt * 128) * CIN;

    float acc[4][4][4];
    u32 sA = (u32)__cvta_generic_to_shared(dsm);
    u32 sB = sA + 2 * TILE_B;
    hmma_gemm(sA, sB, A, CIN, B, CIN, CIN, tid, acc);

    const float* bias = (o == 0) ? bgav : bgah;
    float* dst = g + (size_t)(o * BB + b) * MIDC * NNE + (size_t)nt * 128;
#pragma unroll
    for (int mf = 0; mf < 4; mf++)
#pragma unroll
        for (int nf = 0; nf < 4; nf++)
#pragma unroll
            for (int h = 0; h < 2; h++) {
                int r = wm * 64 + mf * 16 + (lane >> 2) + h * 8;
                int c = wn * 32 + nf * 8 + ((lane & 3) << 1);
                float bval = bias[r];
                *reinterpret_cast<float2*>(dst + (size_t)r * NNE + c) =
                    make_float2(acc[mf][nf][h * 2] + bval, acc[mf][nf][h * 2 + 1] + bval);
            }
}

// ET[sel][b][j][i] = exp(scale * fa[j]·fq[i]); Z[sel][b][i] += column sums.
// grid (it 18, jt 18, b + 8*sel). rows=j, cols=i.
__global__ __launch_bounds__(256, 2) void k_score(
    const __nv_bfloat16* __restrict__ ft, __nv_bfloat16* __restrict__ et,
    float* __restrict__ Z)
{
    extern __shared__ char dsm[];
    __shared__ float zs[2][128];
    int tid = threadIdx.x, lane = tid & 31, wid = tid >> 5;
    int wm = wid & 1, wn = wid >> 1;
    int it = blockIdx.x, jt = blockIdx.y;
    int z = blockIdx.z, b = z & 7, sel = z >> 3;

    const __nv_bfloat16* fa = ft + (size_t)b * NNE * MIDC;
    const __nv_bfloat16* fq = ft + (size_t)(1 + sel) * (size_t)BB * NNE * MIDC
                                 + (size_t)b * NNE * MIDC;
    const __nv_bfloat16* A = fa + (size_t)jt * 128 * MIDC;
    const __nv_bfloat16* B = fq + (size_t)it * 128 * MIDC;

    float acc[4][4][4];
    u32 sA = (u32)__cvta_generic_to_shared(dsm);
    u32 sB = sA + 2 * TILE_B;
    hmma_gemm(sA, sB, A, MIDC, B, MIDC, MIDC, tid, acc);

#pragma unroll
    for (int mf = 0; mf < 4; mf++)
#pragma unroll
        for (int nf = 0; nf < 4; nf++)
#pragma unroll
            for (int e = 0; e < 4; e++)
                acc[mf][nf][e] = __expf(acc[mf][nf][e] * SCALE_S);

    __nv_bfloat16* dst = et + ((size_t)(sel * BB + b) * NNE + (size_t)jt * 128) * NNE
                            + (size_t)it * 128;
#pragma unroll
    for (int mf = 0; mf < 4; mf++)
#pragma unroll
        for (int nf = 0; nf < 4; nf++)
#pragma unroll
            for (int h = 0; h < 2; h++) {
                int r = wm * 64 + mf * 16 + (lane >> 2) + h * 8;
                int c = wn * 32 + nf * 8 + ((lane & 3) << 1);
                *reinterpret_cast<u32*>(dst + (size_t)r * NNE + c) =
                    pack_bf16(acc[mf][nf][h * 2], acc[mf][nf][h * 2 + 1]);
            }

#pragma unroll
    for (int nf = 0; nf < 4; nf++) {
        float s0 = 0.f, s1 = 0.f;
#pragma unroll
        for (int mf = 0; mf < 4; mf++) {
            s0 += acc[mf][nf][0] + acc[mf][nf][2];
            s1 += acc[mf][nf][1] + acc[mf][nf][3];
        }
#pragma unroll
        for (int off = 4; off < 32; off <<= 1) {
            s0 += __shfl_xor_sync(0xffffffffu, s0, off);
            s1 += __shfl_xor_sync(0xffffffffu, s1, off);
        }
        if (lane < 4) {
            int c = wn * 32 + nf * 8 + lane * 2;
            zs[wm][c] = s0;
            zs[wm][c + 1] = s1;
        }
    }
    __syncthreads();
    if (tid < 128)
        atomicAdd(&Z[(size_t)(sel * BB + b) * NNE + (size_t)it * 128 + tid],
                  zs[0][tid] + zs[1][tid]);
}

// oT[sel][b][j][m] = sum_i ET[j][i]·gn[m][i]. grid (jt 18, 1, b+8*sel). rows=j, cols=m.
__global__ __launch_bounds__(256, 2) void k_ogemm(
    const __nv_bfloat16* __restrict__ et, const __nv_bfloat16* __restrict__ gn,
    __nv_bfloat16* __restrict__ oT)
{
    extern __shared__ char dsm[];
    int tid = threadIdx.x, lane = tid & 31, wid = tid >> 5;
    int wm = wid & 1, wn = wid >> 1;
    int jt = blockIdx.x;
    int z = blockIdx.z, b = z & 7, sel = z >> 3;

    const __nv_bfloat16* A = et + ((size_t)(sel * BB + b) * NNE + (size_t)jt * 128) * NNE;
    const __nv_bfloat16* B = gn + (size_t)(sel * BB + b) * MIDC * NNE;

    float acc[4][4][4];
    u32 sA = (u32)__cvta_generic_to_shared(dsm);
    u32 sB = sA + 2 * TILE_B;
    hmma_gemm(sA, sB, A, NNE, B, NNE, NNE, tid, acc);

    __nv_bfloat16* dst = oT + ((size_t)(sel * BB + b) * NNE + (size_t)jt * 128) * MIDC;
#pragma unroll
    for (int mf = 0; mf < 4; mf++)
#pragma unroll
        for (int nf = 0; nf < 4; nf++)
#pragma unroll
            for (int h = 0; h < 2; h++) {
                int r = wm * 64 + mf * 16 + (lane >> 2) + h * 8;
                int c = wn * 32 + nf * 8 + ((lane & 3) << 1);
                *reinterpret_cast<u32*>(dst + (size_t)r * MIDC + c) =
                    pack_bf16(acc[mf][nf][h * 2], acc[mf][nf][h * 2 + 1]);
            }
}

// out[sel][b][cout][n] = Wf·oT^T + bias + x. grid (nt 18, ct 4, b+8*sel). rows=cout, cols=n.
__global__ __launch_bounds__(256, 2) void k_outconv(
    const __nv_bfloat16* __restrict__ Wc, const __nv_bfloat16* __restrict__ oT,
    const float* __restrict__ bfav, const float* __restrict__ bfah,
    const float* __restrict__ x,
    float* __restrict__ out_v, float* __restrict__ out_h)
{
    extern __shared__ char dsm[];
    int tid = threadIdx.x, lane = tid & 31, wid = tid >> 5;
    int wm = wid & 1, wn = wid >> 1;
    int nt = blockIdx.x, ct = blockIdx.y;
    int z = blockIdx.z, b = z & 7, sel = z >> 3;

    const __nv_bfloat16* A = Wc + (size_t)(4 + sel) * 65536 + (size_t)ct * 128 * MIDC;
    const __nv_bfloat16* B = oT + ((size_t)(sel * BB + b) * NNE + (size_t)nt * 128) * MIDC;

    float acc[4][4][4];
    u32 sA = (u32)__cvta_generic_to_shared(dsm);
    u32 sB = sA + 2 * TILE_B;
    hmma_gemm(sA, sB, A, MIDC, B, MIDC, MIDC, tid, acc);

    const float* bias = (sel == 0) ? bfav : bfah;
    float* outp = (sel == 0) ? out_v : out_h;
#pragma unroll
    for (int mf = 0; mf < 4; mf++)
#pragma unroll
        for (int nf = 0; nf < 4; nf++)
#pragma unroll
            for (int h = 0; h < 2; h++) {
                int r = wm * 64 + mf * 16 + (lane >> 2) + h * 8;
                int c = wn * 32 + nf * 8 + ((lane & 3) << 1);
                int cout = ct * 128 + r;
                size_t base = ((size_t)b * CIN + cout) * NNE + (size_t)nt * 128 + c;
                float2 xv = *reinterpret_cast<const float2*>(x + base);
                float bval = bias[cout];
                *reinterpret_cast<float2*>(outp + base) =
                    make_float2(acc[mf][nf][h * 2] + bval + xv.x,
                                acc[mf][nf][h * 2 + 1] + bval + xv.y);
            }
}

// ============================================================================
extern "C" void kernel_launch(void* const* d_in, const int* in_sizes, int n_in,
                              void* d_out, int out_size)
{
    (void)in_sizes; (void)n_in; (void)out_size;

    const float* x    = (const float*)d_in[0];
    const float* x_h  = (const float*)d_in[1];
    const float* x_v  = (const float*)d_in[2];
    const float* Wa   = (const float*)d_in[3];
    const float* ba   = (const float*)d_in[4];
    const float* ga   = (const float*)d_in[5];
    const float* ta   = (const float*)d_in[6];
    const float* Wv   = (const float*)d_in[7];
    const float* bv   = (const float*)d_in[8];
    const float* gv   = (const float*)d_in[9];
    const float* tv   = (const float*)d_in[10];
    const float* Wgav = (const float*)d_in[11];
    const float* bgav = (const float*)d_in[12];
    const float* Wgah = (const float*)d_in[13];
    const float* bgah = (const float*)d_in[14];
    const float* Wfav = (const float*)d_in[15];
    const float* bfav = (const float*)d_in[16];
    const float* Wfah = (const float*)d_in[17];
    const float* bfah = (const float*)d_in[18];

    void* sp = nullptr;
    cudaGetSymbolAddress(&sp, d_scratch);
    char* base = (char*)sp;
    __nv_bfloat16* xT = (__nv_bfloat16*)(base + XT_OFF);
    __nv_bfloat16* ft = (__nv_bfloat16*)(base + FT_OFF);
    float*         g  = (float*)(base + G_OFF);
    __nv_bfloat16* gn = (__nv_bfloat16*)(base + GN_OFF);
    __nv_bfloat16* et = (__nv_bfloat16*)(base + ET_OFF);
    float*         Zp = (float*)(base + Z_OFF);
    __nv_bfloat16* oT = (__nv_bfloat16*)(base + OT_OFF);
    __nv_bfloat16* Wc = (__nv_bfloat16*)(base + WC_OFF);

    float* out_h = (float*)d_out;
    float* out_v = out_h + (size_t)BB * CIN * NNE;

    static int attr_done = 0;
    if (!attr_done) {
        cudaFuncSetAttribute(k_fconv,   cudaFuncAttributeMaxDynamicSharedMemorySize, SMEM_DYN);
        cudaFuncSetAttribute(k_gconv,   cudaFuncAttributeMaxDynamicSharedMemorySize, SMEM_DYN);
        cudaFuncSetAttribute(k_score,   cudaFuncAttributeMaxDynamicSharedMemorySize, SMEM_DYN);
        cudaFuncSetAttribute(k_ogemm,   cudaFuncAttributeMaxDynamicSharedMemorySize, SMEM_DYN);
        cudaFuncSetAttribute(k_outconv, cudaFuncAttributeMaxDynamicSharedMemorySize, SMEM_DYN);
        attr_done = 1;
    }

    // prep: transpose x to bf16 [n][c]; weights to bf16; zero Z
    transpose_x<<<dim3(NNE / 32, CIN / 32, 3 * BB), 256>>>(x, x_v, x_h, xT);
    WC6 w = {{ Wa, Wv, Wgav, Wgah, Wfav, Wfah }};
    conv_weights<<<1536, 256>>>(w, Wc, Zp);

    // input convs
    k_fconv<<<dim3(18, BB, 3), 256, SMEM_DYN>>>(xT, Wc, ba, ga, ta, bv, gv, tv, ft);
    k_gconv<<<dim3(18, BB, 2), 256, SMEM_DYN>>>(xT, Wc, bgav, bgah, g);

    // scores: ET = exp(scale*S)^T, Z = per-query sums
    k_score<<<dim3(18, 18, 16), 256, SMEM_DYN>>>(ft, et, Zp);

    // fold 1/Z into g
    gnorm<<<(2 * BB * MIDC * NNE) / 256, 256>>>(g, Zp, gn);

    // oT = ET·gn^T
    k_ogemm<<<dim3(18, 1, 16), 256, SMEM_DYN>>>(et, gn, oT);

    // output convs + residual
    k_outconv<<<dim3(18, 4, 16), 256, SMEM_DYN>>>(Wc, oT, bfav, bfah, x, out_v, out_h);
}